// round 15
// baseline (speedup 1.0000x reference)
#include <cuda_runtime.h>
#include <cuda_bf16.h>
#include <stdint.h>
#include <math.h>

#define B_  8
#define S_  1024
#define D_  1024
#define H_  16
#define DK  64
#define BH  (B_ * H_)
#define MROWS (B_ * S_)

typedef __nv_bfloat16 bf16;

// bf16 hi/lo planes
__device__ bf16 g_xh[3][(size_t)MROWS * D_];
__device__ bf16 g_xl[3][(size_t)MROWS * D_];
__device__ bf16 g_wh[3][(size_t)H_ * D_ * DK];
__device__ bf16 g_wl[3][(size_t)H_ * D_ * DK];
__device__ bf16 g_woh[(size_t)D_ * D_];
__device__ bf16 g_wol[(size_t)D_ * D_];
__device__ bf16 g_qh[(size_t)BH * S_ * DK];
__device__ bf16 g_ql[(size_t)BH * S_ * DK];
__device__ bf16 g_kh[(size_t)BH * S_ * DK];
__device__ bf16 g_kl[(size_t)BH * S_ * DK];
__device__ bf16 g_vh[(size_t)BH * S_ * DK];
__device__ bf16 g_vl[(size_t)BH * S_ * DK];
__device__ bf16 g_ch[(size_t)BH * S_ * DK];
__device__ bf16 g_cl[(size_t)BH * S_ * DK];
__device__ float g_attn[(size_t)BH * S_ * S_];

// ---------------------------------------------------------------------------
__device__ __forceinline__ uint32_t s2u(const void* p) {
    uint32_t a;
    asm("{ .reg .u64 t; cvta.to.shared.u64 t, %1; cvt.u32.u64 %0, t; }"
        : "=r"(a) : "l"(p));
    return a;
}
__device__ __forceinline__ void ldsm4(uint32_t* r, uint32_t a) {
    asm volatile("ldmatrix.sync.aligned.m8n8.x4.shared.b16 {%0,%1,%2,%3}, [%4];"
        : "=r"(r[0]), "=r"(r[1]), "=r"(r[2]), "=r"(r[3]) : "r"(a));
}
__device__ __forceinline__ void ldsm4t(uint32_t* r, uint32_t a) {
    asm volatile("ldmatrix.sync.aligned.m8n8.x4.trans.shared.b16 {%0,%1,%2,%3}, [%4];"
        : "=r"(r[0]), "=r"(r[1]), "=r"(r[2]), "=r"(r[3]) : "r"(a));
}
__device__ __forceinline__ void mmabf(float* c, const uint32_t* a, const uint32_t* b) {
    asm volatile("mma.sync.aligned.m16n8k16.row.col.f32.bf16.bf16.f32 "
        "{%0,%1,%2,%3}, {%4,%5,%6,%7}, {%8,%9}, {%0,%1,%2,%3};"
        : "+f"(c[0]), "+f"(c[1]), "+f"(c[2]), "+f"(c[3])
        : "r"(a[0]), "r"(a[1]), "r"(a[2]), "r"(a[3]), "r"(b[0]), "r"(b[1]));
}
__device__ __forceinline__ uint32_t packbf(float lo_e, float hi_e) {
    uint32_t r;
    asm("cvt.rn.bf16x2.f32 %0, %1, %2;" : "=r"(r) : "f"(hi_e), "f"(lo_e));
    return r;
}
__device__ __forceinline__ void cpa16(uint32_t dst, const void* src) {
    asm volatile("cp.async.cg.shared.global [%0], [%1], 16;" :: "r"(dst), "l"(src));
}
#define CPA_COMMIT() asm volatile("cp.async.commit_group;" ::: "memory")
#define CPA_WAIT(n)  asm volatile("cp.async.wait_group %0;" :: "n"(n) : "memory")

#define ASTR 40
#define BSTR 72      // attn kernel B stride
#define BW   136     // GEMM B stride (128 + 8 pad)

// ===========================================================================
// GEMM core: 128x128x32 tile, 256 threads (4m x 2n warps, warp 32x64)
// 3-stage k32 pipeline, single barrier per chunk.
// ===========================================================================
#define ABP (128 * ASTR)               // 5120 elems per A plane
#define BBP (32 * BW)                  // 4352 elems per B plane
#define STGP (2 * ABP + 2 * BBP)       // 18944 elems per stage
#define SMEM_P3 (3 * STGP * 2)         // 113664 bytes

// one k32 chunk for a 32x64 warp tile: 24 ldsm, 96 mma
__device__ __forceinline__ void warp_chunk128(
    const bf16* Ah, const bf16* Al, const bf16* Bh, const bf16* Bl,
    int m_off, int n_off, int lane, float acc[2][8][4])
{
    #pragma unroll
    for (int kk = 0; kk < 32; kk += 16) {
        uint32_t a[2][4], b0[4][4], b1[4][4];
        #pragma unroll
        for (int mi = 0; mi < 2; mi++)
            ldsm4(a[mi], s2u(Ah + (m_off + mi * 16 + (lane & 15)) * ASTR + kk + (lane >> 4) * 8));
        #pragma unroll
        for (int j = 0; j < 4; j++)
            ldsm4t(b0[j], s2u(Bh + (kk + (lane & 15)) * BW + n_off + j * 16 + (lane >> 4) * 8));
        #pragma unroll
        for (int mi = 0; mi < 2; mi++)
            #pragma unroll
            for (int nj = 0; nj < 8; nj++)
                mmabf(acc[mi][nj], a[mi], &b0[nj >> 1][(nj & 1) * 2]);
        #pragma unroll
        for (int j = 0; j < 4; j++)
            ldsm4t(b1[j], s2u(Bl + (kk + (lane & 15)) * BW + n_off + j * 16 + (lane >> 4) * 8));
        #pragma unroll
        for (int mi = 0; mi < 2; mi++)
            #pragma unroll
            for (int nj = 0; nj < 8; nj++)
                mmabf(acc[mi][nj], a[mi], &b1[nj >> 1][(nj & 1) * 2]);
        #pragma unroll
        for (int mi = 0; mi < 2; mi++)
            ldsm4(a[mi], s2u(Al + (m_off + mi * 16 + (lane & 15)) * ASTR + kk + (lane >> 4) * 8));
        #pragma unroll
        for (int mi = 0; mi < 2; mi++)
            #pragma unroll
            for (int nj = 0; nj < 8; nj++)
                mmabf(acc[mi][nj], a[mi], &b0[nj >> 1][(nj & 1) * 2]);
    }
}

// ===========================================================================
// cvt_all
// ===========================================================================
#define XU (MROWS * D_ / 4)
#define WU (H_ * D_ * DK / 4)
#define CVT_UNITS (3 * XU + 4 * WU)

__global__ __launch_bounds__(256) void cvt_all(
    const float* __restrict__ q, const float* __restrict__ k,
    const float* __restrict__ v, const float* __restrict__ wq,
    const float* __restrict__ wk, const float* __restrict__ wv,
    const float* __restrict__ wo)
{
    size_t u = (size_t)blockIdx.x * 256 + threadIdx.x;
    if (u >= CVT_UNITS) return;
    const float* src;
    bf16 *dh, *dl;
    size_t off;
    if (u < 3 * (size_t)XU) {
        int z = (int)(u / XU);
        off = (u - (size_t)z * XU) * 4;
        src = (z == 0) ? q : (z == 1) ? k : v;
        dh = g_xh[z]; dl = g_xl[z];
    } else {
        size_t r = u - 3 * (size_t)XU;
        int z = (int)(r / WU);
        off = (r - (size_t)z * WU) * 4;
        if (z < 3) {
            src = (z == 0) ? wq : (z == 1) ? wk : wv;
            dh = g_wh[z]; dl = g_wl[z];
        } else {
            src = wo; dh = g_woh; dl = g_wol;
        }
    }
    float4 vv = *(const float4*)(src + off);
    uint32_t h0 = packbf(vv.x, vv.y), h1 = packbf(vv.z, vv.w);
    float hx = __uint_as_float(h0 << 16), hy = __uint_as_float(h0 & 0xffff0000u);
    float hz = __uint_as_float(h1 << 16), hw = __uint_as_float(h1 & 0xffff0000u);
    uint32_t l0 = packbf(vv.x - hx, vv.y - hy), l1 = packbf(vv.z - hz, vv.w - hw);
    *(uint2*)(dh + off) = make_uint2(h0, h1);
    *(uint2*)(dl + off) = make_uint2(l0, l1);
}

// ===========================================================================
// proj: grid (D_/128, MROWS/128, 3), block 256, 3-stage k32, single barrier
// ===========================================================================
__global__ __launch_bounds__(256, 2) void proj_cp(
    const float* __restrict__ bq, const float* __restrict__ bk,
    const float* __restrict__ bv)
{
    extern __shared__ bf16 sm[];
    const uint32_t smb = s2u(sm);
    const int tid = threadIdx.x, w = tid >> 5, lane = tid & 31;
    const int n0 = blockIdx.x * 128, m0 = blockIdx.y * 128, z = blockIdx.z;
    const bf16* Xh = g_xh[z];
    const bf16* Xl = g_xl[z];
    const bf16* Wph = g_wh[z];
    const bf16* Wpl = g_wl[z];
    const float* bias = (z == 0) ? bq : (z == 1) ? bk : bv;
    bf16* outh = (z == 0) ? g_qh : (z == 1) ? g_kh : g_vh;
    bf16* outl = (z == 0) ? g_ql : (z == 1) ? g_kl : g_vl;
    const int m_off = (w & 3) * 32, n_off = (w >> 2) * 64;
    float acc[2][8][4] = {};

    auto pref = [&](int buf, int k0) {
        uint32_t base = smb + buf * (STGP * 2);
        #pragma unroll
        for (int i = 0; i < 4; i++) {                 // A: 128x32, hi+lo
            int lin = tid + i * 256;
            int pl = lin >> 9, rem = lin & 511, r = rem >> 2, c4 = rem & 3;
            const bf16* srcp = (pl ? Xl : Xh) + (size_t)(m0 + r) * D_ + k0 + c4 * 8;
            cpa16(base + (pl * ABP + r * ASTR + c4 * 8) * 2, srcp);
        }
        #pragma unroll
        for (int i = 0; i < 4; i++) {                 // B: 32x128, hi+lo
            int lin = tid + i * 256;
            int pl = lin >> 9, rem = lin & 511, r = rem >> 4, c8 = rem & 15;
            int col = n0 + c8 * 8;
            int h = col >> 6, j = col & 63;
            const bf16* srcp = (pl ? Wpl : Wph) + ((size_t)h * D_ + k0 + r) * DK + j;
            cpa16(base + (2 * ABP + pl * BBP + r * BW + c8 * 8) * 2, srcp);
        }
        CPA_COMMIT();
    };

    pref(0, 0);
    pref(1, 32);
    int buf = 0;
    for (int c = 0; c < 32; c++) {
        if (c < 31) { CPA_WAIT(1); } else { CPA_WAIT(0); }
        __syncthreads();
        if (c + 2 < 32) {
            int nb = buf + 2; if (nb >= 3) nb -= 3;
            pref(nb, (c + 2) * 32);
        }
        bf16* st = sm + buf * STGP;
        warp_chunk128(st, st + ABP, st + 2 * ABP, st + 2 * ABP + BBP,
                      m_off, n_off, lane, acc);
        if (++buf == 3) buf = 0;
    }

    const int g = lane >> 2, q = lane & 3;
    const int h = (n0 + n_off) >> 6;                 // warp's 64 cols = one head
    #pragma unroll
    for (int mi = 0; mi < 2; mi++) {
        int m = m0 + m_off + mi * 16 + g;
        int b = m >> 10, s = m & 1023;
        size_t base0 = (((size_t)(b * H_ + h)) * S_ + s) * DK;
        size_t base1 = (((size_t)(b * H_ + h)) * S_ + s + 8) * DK;
        #pragma unroll
        for (int nj = 0; nj < 8; nj++) {
            int j0 = nj * 8 + q * 2;
            float bb0 = bias[h * DK + j0], bb1 = bias[h * DK + j0 + 1];
            float v0 = acc[mi][nj][0] + bb0, v1 = acc[mi][nj][1] + bb1;
            float v2 = acc[mi][nj][2] + bb0, v3 = acc[mi][nj][3] + bb1;
            uint32_t hp0 = packbf(v0, v1), hp1 = packbf(v2, v3);
            float h0 = __uint_as_float(hp0 << 16), h1 = __uint_as_float(hp0 & 0xffff0000u);
            float h2 = __uint_as_float(hp1 << 16), h3 = __uint_as_float(hp1 & 0xffff0000u);
            uint32_t lp0 = packbf(v0 - h0, v1 - h1), lp1 = packbf(v2 - h2, v3 - h3);
            *(uint32_t*)&outh[base0 + j0] = hp0;
            *(uint32_t*)&outl[base0 + j0] = lp0;
            *(uint32_t*)&outh[base1 + j0] = hp1;
            *(uint32_t*)&outl[base1 + j0] = lp1;
        }
    }
}

// ===========================================================================
// outproj: grid (D_/128, MROWS/128), block 256, 3-stage k32, single barrier
// ===========================================================================
__global__ __launch_bounds__(256, 2) void outproj_cp(
    const float* __restrict__ bo, float* __restrict__ out)
{
    extern __shared__ bf16 sm[];
    const uint32_t smb = s2u(sm);
    const int tid = threadIdx.x, w = tid >> 5, lane = tid & 31;
    const int n0 = blockIdx.x * 128, m0 = blockIdx.y * 128;
    const int m_off = (w & 3) * 32, n_off = (w >> 2) * 64;
    float acc[2][8][4] = {};

    auto pref = [&](int buf, int k0) {
        uint32_t base = smb + buf * (STGP * 2);
        const int h = k0 >> 6, j0 = k0 & 63;
        #pragma unroll
        for (int i = 0; i < 4; i++) {                 // A: ctx gather 128x32
            int lin = tid + i * 256;
            int pl = lin >> 9, rem = lin & 511, r = rem >> 2, c4 = rem & 3;
            int m = m0 + r;
            int b = m >> 10, s = m & 1023;
            const bf16* srcp = (pl ? g_cl : g_ch) +
                (((size_t)b * H_ + h) * S_ + s) * DK + j0 + c4 * 8;
            cpa16(base + (pl * ABP + r * ASTR + c4 * 8) * 2, srcp);
        }
        #pragma unroll
        for (int i = 0; i < 4; i++) {                 // B: Wo 32x128
            int lin = tid + i * 256;
            int pl = lin >> 9, rem = lin & 511, r = rem >> 4, c8 = rem & 15;
            const bf16* srcp = (pl ? g_wol : g_woh) + (size_t)(k0 + r) * D_ + n0 + c8 * 8;
            cpa16(base + (2 * ABP + pl * BBP + r * BW + c8 * 8) * 2, srcp);
        }
        CPA_COMMIT();
    };

    pref(0, 0);
    pref(1, 32);
    int buf = 0;
    for (int c = 0; c < 32; c++) {
        if (c < 31) { CPA_WAIT(1); } else { CPA_WAIT(0); }
        __syncthreads();
        if (c + 2 < 32) {
            int nb = buf + 2; if (nb >= 3) nb -= 3;
            pref(nb, (c + 2) * 32);
        }
        bf16* st = sm + buf * STGP;
        warp_chunk128(st, st + ABP, st + 2 * ABP, st + 2 * ABP + BBP,
                      m_off, n_off, lane, acc);
        if (++buf == 3) buf = 0;
    }

    const int g = lane >> 2, q = lane & 3;
    #pragma unroll
    for (int mi = 0; mi < 2; mi++) {
        int m = m0 + m_off + mi * 16 + g;
        float* d0 = out + (size_t)m * D_;
        float* d1 = out + (size_t)(m + 8) * D_;
        #pragma unroll
        for (int nj = 0; nj < 8; nj++) {
            int col = n0 + n_off + nj * 8 + q * 2;
            float bb0 = bo[col], bb1 = bo[col + 1];
            *(float2*)&d0[col] = make_float2(acc[mi][nj][0] + bb0, acc[mi][nj][1] + bb1);
            *(float2*)&d1[col] = make_float2(acc[mi][nj][2] + bb0, acc[mi][nj][3] + bb1);
        }
    }
}

// ===========================================================================
// Fused attention (unchanged from R12/R14)
// ===========================================================================
#define SC_STRW 1036
#define SC_ROWB (SC_STRW * 4)
#define SC_BYTES (32 * SC_ROWB)
#define KBUF_OFF SC_BYTES
#define KPLANE 18432
#define KBUF_SZ (2 * KPLANE)
#define Q_OFF (KBUF_OFF + 2 * KBUF_SZ)
#define FUSED_SMEM (Q_OFF + 2 * 4608)

__device__ __forceinline__ void attn_prefetch(
    char* smem, int bufidx, const bf16* ph, const bf16* pl,
    size_t bhS, int t0, int tid)
{
    uint32_t buf = s2u(smem + KBUF_OFF + bufidx * KBUF_SZ);
    #pragma unroll
    for (int i = 0; i < 8; i++) {
        int cid = tid + i * 256;
        int plane = cid >> 10, rem = cid & 1023;
        int row = rem >> 3, c16 = rem & 7;
        const bf16* src = (plane ? pl : ph) + (bhS + t0 + row) * DK + c16 * 8;
        cpa16(buf + plane * KPLANE + row * 144 + c16 * 16, src);
    }
    CPA_COMMIT();
}

__global__ __launch_bounds__(256) void attn_fused(
    const bf16* __restrict__ qh, const bf16* __restrict__ ql,
    const bf16* __restrict__ kh, const bf16* __restrict__ kl,
    const bf16* __restrict__ vh, const bf16* __restrict__ vl,
    float* __restrict__ attn, bf16* __restrict__ ctxh, bf16* __restrict__ ctxl)
{
    extern __shared__ char smem[];
    float* sc = (float*)smem;
    bf16* QH = (bf16*)(smem + Q_OFF);
    bf16* QL = (bf16*)(smem + Q_OFF + 4608);
    const uint32_t sc_base = s2u(smem);

    const int tid = threadIdx.x, w = tid >> 5, lane = tid & 31;
    const int s0 = blockIdx.x * 32;
    const int bh = blockIdx.y;
    const size_t bhS = (size_t)bh * S_;
    const int wm = w & 1, wn = w >> 1;
    const int g = lane >> 2, q = lane & 3;

    #pragma unroll
    for (int i = 0; i < 2; i++) {
        int lin = tid + i * 256;
        int plane = lin >> 8;
        int rem = lin & 255;
        int row = rem >> 3;
        int c16 = rem & 7;
        const bf16* src = (plane ? ql : qh) + (bhS + s0 + row) * DK + c16 * 8;
        bf16* dstp = (plane ? QL : QH) + row * BSTR + c16 * 8;
        *(uint4*)dstp = *(const uint4*)src;
    }

    attn_prefetch(smem, 0, kh, kl, bhS, 0, tid);
    attn_prefetch(smem, 1, kh, kl, bhS, 128, tid);
    __syncthreads();

    uint32_t aqh[4][4], aql[4][4];
    #pragma unroll
    for (int k4 = 0; k4 < 4; k4++) {
        ldsm4(aqh[k4], s2u(QH + (wm * 16 + (lane & 15)) * BSTR + k4 * 16 + (lane >> 4) * 8));
        ldsm4(aql[k4], s2u(QL + (wm * 16 + (lane & 15)) * BSTR + k4 * 16 + (lane >> 4) * 8));
    }

    for (int c = 0; c < 8; c++) {
        if (c < 7) { CPA_WAIT(1); } else { CPA_WAIT(0); }
        __syncthreads();

        bf16* KHb = (bf16*)(smem + KBUF_OFF + (c & 1) * KBUF_SZ);
        bf16* KLb = (bf16*)(smem + KBUF_OFF + (c & 1) * KBUF_SZ + KPLANE);
        float acc[4][4] = {};
        #pragma unroll
        for (int k4 = 0; k4 < 4; k4++) {
            uint32_t bh4[2][4], bl4[2][4];
            #pragma unroll
            for (int j = 0; j < 2; j++)
                ldsm4(bh4[j], s2u(KHb + (wn * 32 + j * 16 + (lane & 7) + ((lane >> 4) << 3)) * BSTR
                                  + k4 * 16 + ((lane >> 3) & 1) * 8));
            #pragma unroll
            for (int nj = 0; nj < 4; nj++)
                mmabf(acc[nj], aqh[k4], &bh4[nj >> 1][(nj & 1) * 2]);
            #pragma unroll
            for (int j = 0; j < 2; j++)
                ldsm4(bl4[j], s2u(KLb + (wn * 32 + j * 16 + (lane & 7) + ((lane >> 4) << 3)) * BSTR
                                  + k4 * 16 + ((lane >> 3) & 1) * 8));
            #pragma unroll
            for (int nj = 0; nj < 4; nj++)
                mmabf(acc[nj], aqh[k4], &bl4[nj >> 1][(nj & 1) * 2]);
            #pragma unroll
            for (int nj = 0; nj < 4; nj++)
                mmabf(acc[nj], aql[k4], &bh4[nj >> 1][(nj & 1) * 2]);
        }
        #pragma unroll
        for (int nj = 0; nj < 4; nj++) {
            int col = c * 128 + wn * 32 + nj * 8 + q * 2;
            *(float2*)&sc[(wm * 16 + g) * SC_STRW + col] =
                make_float2(acc[nj][0] * 0.125f, acc[nj][1] * 0.125f);
            *(float2*)&sc[(wm * 16 + g + 8) * SC_STRW + col] =
                make_float2(acc[nj][2] * 0.125f, acc[nj][3] * 0.125f);
        }
        __syncthreads();
        if (c + 2 < 8)
            attn_prefetch(smem, c & 1, kh, kl, bhS, (c + 2) * 128, tid);
    }

    attn_prefetch(smem, 0, vh, vl, bhS, 0, tid);
    attn_prefetch(smem, 1, vh, vl, bhS, 128, tid);

    #pragma unroll
    for (int rr = 0; rr < 4; rr++) {
        const int row = w * 4 + rr;
        float* prow = sc + row * SC_STRW;
        char* rowb = smem + row * SC_ROWB;
        float4 v[8];
        float mx = -1e30f;
        #pragma unroll
        for (int j = 0; j < 8; j++) {
            v[j] = *(const float4*)&prow[lane * 4 + j * 128];
            mx = fmaxf(mx, fmaxf(fmaxf(v[j].x, v[j].y), fmaxf(v[j].z, v[j].w)));
        }
        #pragma unroll
        for (int off = 16; off > 0; off >>= 1)
            mx = fmaxf(mx, __shfl_xor_sync(0xffffffffu, mx, off));
        float sum = 0.f;
        #pragma unroll
        for (int j = 0; j < 8; j++) {
            v[j].x = __expf(v[j].x - mx); v[j].y = __expf(v[j].y - mx);
            v[j].z = __expf(v[j].z - mx); v[j].w = __expf(v[j].w - mx);
            sum += (v[j].x + v[j].y) + (v[j].z + v[j].w);
        }
        #pragma unroll
        for (int off = 16; off > 0; off >>= 1)
            sum += __shfl_xor_sync(0xffffffffu, sum, off);
        const float inv = 1.0f / sum;
        float* grow = attn + (bhS + s0 + row) * S_;
        #pragma unroll
        for (int j = 0; j < 8; j++) {
            float4 o = make_float4(v[j].x * inv, v[j].y * inv, v[j].z * inv, v[j].w * inv);
            *(float4*)&grow[lane * 4 + j * 128] = o;
            uint32_t h01 = packbf(o.x, o.y);
            uint32_t h23 = packbf(o.z, o.w);
            float hx = __uint_as_float(h01 << 16), hy = __uint_as_float(h01 & 0xffff0000u);
            float hz = __uint_as_float(h23 << 16), hw = __uint_as_float(h23 & 0xffff0000u);
            uint32_t l01 = packbf(o.x - hx, o.y - hy);
            uint32_t l23 = packbf(o.z - hz, o.w - hw);
            *(uint2*)(rowb + lane * 8 + j * 256)        = make_uint2(h01, h23);
            *(uint2*)(rowb + 2048 + lane * 8 + j * 256) = make_uint2(l01, l23);
        }
    }
    __syncthreads();

    float acc2[2][4] = {};
    for (int c = 0; c < 8; c++) {
        if (c < 7) { CPA_WAIT(1); } else { CPA_WAIT(0); }
        __syncthreads();

        bf16* VHb = (bf16*)(smem + KBUF_OFF + (c & 1) * KBUF_SZ);
        bf16* VLb = (bf16*)(smem + KBUF_OFF + (c & 1) * KBUF_SZ + KPLANE);
        #pragma unroll
        for (int k4 = 0; k4 < 8; k4++) {
            int colb = c * 128 + k4 * 16;
            uint32_t abase = sc_base + (wm * 16 + (lane & 15)) * SC_ROWB
                             + (colb + (lane >> 4) * 8) * 2;
            uint32_t ah[4], al[4];
            ldsm4(ah, abase);
            ldsm4(al, abase + 2048);

            uint32_t bhf[4], blf[4];
            ldsm4t(bhf, s2u(VHb + (k4 * 16 + (lane & 15)) * BSTR + wn * 16 + (lane >> 4) * 8));
            ldsm4t(blf, s2u(VLb + (k4 * 16 + (lane & 15)) * BSTR + wn * 16 + (lane >> 4) * 8));
            #pragma unroll
            for (int nj = 0; nj < 2; nj++) {
                mmabf(acc2[nj], ah, &bhf[nj * 2]);
                mmabf(acc2[nj], ah, &blf[nj * 2]);
                mmabf(acc2[nj], al, &bhf[nj * 2]);
            }
        }
        __syncthreads();
        if (c + 2 < 8)
            attn_prefetch(smem, c & 1, vh, vl, bhS, (c + 2) * 128, tid);
    }

    #pragma unroll
    for (int nj = 0; nj < 2; nj++) {
        int col = wn * 16 + nj * 8 + q * 2;
        size_t i0 = (bhS + s0 + wm * 16 + g) * DK + col;
        size_t i1 = (bhS + s0 + wm * 16 + g + 8) * DK + col;
        uint32_t hp0 = packbf(acc2[nj][0], acc2[nj][1]);
        uint32_t hp1 = packbf(acc2[nj][2], acc2[nj][3]);
        float h0 = __uint_as_float(hp0 << 16), h1 = __uint_as_float(hp0 & 0xffff0000u);
        float h2 = __uint_as_float(hp1 << 16), h3 = __uint_as_float(hp1 & 0xffff0000u);
        uint32_t lp0 = packbf(acc2[nj][0] - h0, acc2[nj][1] - h1);
        uint32_t lp1 = packbf(acc2[nj][2] - h2, acc2[nj][3] - h3);
        *(uint32_t*)&ctxh[i0] = hp0;
        *(uint32_t*)&ctxl[i0] = lp0;
        *(uint32_t*)&ctxh[i1] = hp1;
        *(uint32_t*)&ctxl[i1] = lp1;
    }
}

// ---------------------------------------------------------------------------
extern "C" void kernel_launch(void* const* d_in, const int* in_sizes, int n_in,
                              void* d_out, int out_size)
{
    const float* query = (const float*)d_in[0];
    const float* key   = (const float*)d_in[1];
    const float* value = (const float*)d_in[2];
    const float* Wq    = (const float*)d_in[3];
    const float* bq    = (const float*)d_in[4];
    const float* Wk    = (const float*)d_in[5];
    const float* bk    = (const float*)d_in[6];
    const float* Wv    = (const float*)d_in[7];
    const float* bv    = (const float*)d_in[8];
    const float* Wo    = (const float*)d_in[9];
    const float* bo    = (const float*)d_in[10];
    float* out = (float*)d_out;

    bf16 *qh, *ql, *kh, *kl, *vh, *vl, *ch, *cl;
    float *attn_scratch;
    cudaGetSymbolAddress((void**)&qh, g_qh);
    cudaGetSymbolAddress((void**)&ql, g_ql);
    cudaGetSymbolAddress((void**)&kh, g_kh);
    cudaGetSymbolAddress((void**)&kl, g_kl);
    cudaGetSymbolAddress((void**)&vh, g_vh);
    cudaGetSymbolAddress((void**)&vl, g_vl);
    cudaGetSymbolAddress((void**)&ch, g_ch);
    cudaGetSymbolAddress((void**)&cl, g_cl);
    cudaGetSymbolAddress((void**)&attn_scratch, g_attn);

    const size_t out_elems  = (size_t)B_ * S_ * D_;
    const size_t attn_elems = (size_t)BH * S_ * S_;
    float* attn = ((size_t)out_size >= out_elems + attn_elems)
                      ? (out + out_elems) : attn_scratch;

    static int smem_set = 0;
    if (!smem_set) {
        cudaFuncSetAttribute(proj_cp, cudaFuncAttributeMaxDynamicSharedMemorySize, SMEM_P3);
        cudaFuncSetAttribute(outproj_cp, cudaFuncAttributeMaxDynamicSharedMemorySize, SMEM_P3);
        cudaFuncSetAttribute(attn_fused, cudaFuncAttributeMaxDynamicSharedMemorySize, FUSED_SMEM);
        smem_set = 1;
    }

    cvt_all<<<(CVT_UNITS + 255) / 256, 256>>>(query, key, value, Wq, Wk, Wv, Wo);
    proj_cp<<<dim3(D_ / 128, MROWS / 128, 3), 256, SMEM_P3>>>(bq, bk, bv);
    attn_fused<<<dim3(S_ / 32, BH), 256, FUSED_SMEM>>>(qh, ql, kh, kl, vh, vl, attn, ch, cl);
    outproj_cp<<<dim3(D_ / 128, MROWS / 128), 256, SMEM_P3>>>(bo, out);
}

// round 16
// speedup vs baseline: 1.0177x; 1.0177x over previous
#include <cuda_runtime.h>
#include <cuda_bf16.h>
#include <stdint.h>
#include <math.h>

#define B_  8
#define S_  1024
#define D_  1024
#define H_  16
#define DK  64
#define BH  (B_ * H_)
#define MROWS (B_ * S_)

typedef __nv_bfloat16 bf16;

// bf16 hi/lo planes
__device__ bf16 g_xh[3][(size_t)MROWS * D_];
__device__ bf16 g_xl[3][(size_t)MROWS * D_];
__device__ bf16 g_wh[3][(size_t)H_ * D_ * DK];
__device__ bf16 g_wl[3][(size_t)H_ * D_ * DK];
__device__ bf16 g_woh[(size_t)D_ * D_];
__device__ bf16 g_wol[(size_t)D_ * D_];
__device__ bf16 g_qh[(size_t)BH * S_ * DK];
__device__ bf16 g_ql[(size_t)BH * S_ * DK];
__device__ bf16 g_kh[(size_t)BH * S_ * DK];
__device__ bf16 g_kl[(size_t)BH * S_ * DK];
__device__ bf16 g_vh[(size_t)BH * S_ * DK];
__device__ bf16 g_vl[(size_t)BH * S_ * DK];
__device__ bf16 g_ch[(size_t)BH * S_ * DK];
__device__ bf16 g_cl[(size_t)BH * S_ * DK];
__device__ float g_attn[(size_t)BH * S_ * S_];

// ---------------------------------------------------------------------------
__device__ __forceinline__ uint32_t s2u(const void* p) {
    uint32_t a;
    asm("{ .reg .u64 t; cvta.to.shared.u64 t, %1; cvt.u32.u64 %0, t; }"
        : "=r"(a) : "l"(p));
    return a;
}
__device__ __forceinline__ void ldsm4(uint32_t* r, uint32_t a) {
    asm volatile("ldmatrix.sync.aligned.m8n8.x4.shared.b16 {%0,%1,%2,%3}, [%4];"
        : "=r"(r[0]), "=r"(r[1]), "=r"(r[2]), "=r"(r[3]) : "r"(a));
}
__device__ __forceinline__ void ldsm4t(uint32_t* r, uint32_t a) {
    asm volatile("ldmatrix.sync.aligned.m8n8.x4.trans.shared.b16 {%0,%1,%2,%3}, [%4];"
        : "=r"(r[0]), "=r"(r[1]), "=r"(r[2]), "=r"(r[3]) : "r"(a));
}
__device__ __forceinline__ void mmabf(float* c, const uint32_t* a, const uint32_t* b) {
    asm volatile("mma.sync.aligned.m16n8k16.row.col.f32.bf16.bf16.f32 "
        "{%0,%1,%2,%3}, {%4,%5,%6,%7}, {%8,%9}, {%0,%1,%2,%3};"
        : "+f"(c[0]), "+f"(c[1]), "+f"(c[2]), "+f"(c[3])
        : "r"(a[0]), "r"(a[1]), "r"(a[2]), "r"(a[3]), "r"(b[0]), "r"(b[1]));
}
__device__ __forceinline__ uint32_t packbf(float lo_e, float hi_e) {
    uint32_t r;
    asm("cvt.rn.bf16x2.f32 %0, %1, %2;" : "=r"(r) : "f"(hi_e), "f"(lo_e));
    return r;
}
__device__ __forceinline__ void cpa16(uint32_t dst, const void* src) {
    asm volatile("cp.async.cg.shared.global [%0], [%1], 16;" :: "r"(dst), "l"(src));
}
#define CPA_COMMIT() asm volatile("cp.async.commit_group;" ::: "memory")
#define CPA_WAIT(n)  asm volatile("cp.async.wait_group %0;" :: "n"(n) : "memory")

#define ASTR 40
#define BSTR 72      // attn kernel B stride
#define BW   136     // GEMM B stride (128 + 8 pad)

// ===========================================================================
// GEMM core: 128x128x32 tile, 256 threads (4m x 2n warps, warp 32x64)
// ===========================================================================
#define ABP (128 * ASTR)               // 5120 elems per A plane
#define BBP (32 * BW)                  // 4352 elems per B plane
#define STGP (2 * ABP + 2 * BBP)       // 18944 elems per stage
#define SMEM_P2 (2 * STGP * 2)         // 75776 bytes (proj: 2-stage)
#define SMEM_P3 (3 * STGP * 2)         // 113664 bytes (outproj: 3-stage)

// one k32 chunk for a 32x64 warp tile: 24 ldsm, 96 mma
__device__ __forceinline__ void warp_chunk128(
    const bf16* Ah, const bf16* Al, const bf16* Bh, const bf16* Bl,
    int m_off, int n_off, int lane, float acc[2][8][4])
{
    #pragma unroll
    for (int kk = 0; kk < 32; kk += 16) {
        uint32_t a[2][4], b0[4][4], b1[4][4];
        #pragma unroll
        for (int mi = 0; mi < 2; mi++)
            ldsm4(a[mi], s2u(Ah + (m_off + mi * 16 + (lane & 15)) * ASTR + kk + (lane >> 4) * 8));
        #pragma unroll
        for (int j = 0; j < 4; j++)
            ldsm4t(b0[j], s2u(Bh + (kk + (lane & 15)) * BW + n_off + j * 16 + (lane >> 4) * 8));
        #pragma unroll
        for (int mi = 0; mi < 2; mi++)
            #pragma unroll
            for (int nj = 0; nj < 8; nj++)
                mmabf(acc[mi][nj], a[mi], &b0[nj >> 1][(nj & 1) * 2]);
        #pragma unroll
        for (int j = 0; j < 4; j++)
            ldsm4t(b1[j], s2u(Bl + (kk + (lane & 15)) * BW + n_off + j * 16 + (lane >> 4) * 8));
        #pragma unroll
        for (int mi = 0; mi < 2; mi++)
            #pragma unroll
            for (int nj = 0; nj < 8; nj++)
                mmabf(acc[mi][nj], a[mi], &b1[nj >> 1][(nj & 1) * 2]);
        #pragma unroll
        for (int mi = 0; mi < 2; mi++)
            ldsm4(a[mi], s2u(Al + (m_off + mi * 16 + (lane & 15)) * ASTR + kk + (lane >> 4) * 8));
        #pragma unroll
        for (int mi = 0; mi < 2; mi++)
            #pragma unroll
            for (int nj = 0; nj < 8; nj++)
                mmabf(acc[mi][nj], a[mi], &b0[nj >> 1][(nj & 1) * 2]);
    }
}

// ===========================================================================
// cvt_all
// ===========================================================================
#define XU (MROWS * D_ / 4)
#define WU (H_ * D_ * DK / 4)
#define CVT_UNITS (3 * XU + 4 * WU)

__global__ __launch_bounds__(256) void cvt_all(
    const float* __restrict__ q, const float* __restrict__ k,
    const float* __restrict__ v, const float* __restrict__ wq,
    const float* __restrict__ wk, const float* __restrict__ wv,
    const float* __restrict__ wo)
{
    size_t u = (size_t)blockIdx.x * 256 + threadIdx.x;
    if (u >= CVT_UNITS) return;
    const float* src;
    bf16 *dh, *dl;
    size_t off;
    if (u < 3 * (size_t)XU) {
        int z = (int)(u / XU);
        off = (u - (size_t)z * XU) * 4;
        src = (z == 0) ? q : (z == 1) ? k : v;
        dh = g_xh[z]; dl = g_xl[z];
    } else {
        size_t r = u - 3 * (size_t)XU;
        int z = (int)(r / WU);
        off = (r - (size_t)z * WU) * 4;
        if (z < 3) {
            src = (z == 0) ? wq : (z == 1) ? wk : wv;
            dh = g_wh[z]; dl = g_wl[z];
        } else {
            src = wo; dh = g_woh; dl = g_wol;
        }
    }
    float4 vv = *(const float4*)(src + off);
    uint32_t h0 = packbf(vv.x, vv.y), h1 = packbf(vv.z, vv.w);
    float hx = __uint_as_float(h0 << 16), hy = __uint_as_float(h0 & 0xffff0000u);
    float hz = __uint_as_float(h1 << 16), hw = __uint_as_float(h1 & 0xffff0000u);
    uint32_t l0 = packbf(vv.x - hx, vv.y - hy), l1 = packbf(vv.z - hz, vv.w - hw);
    *(uint2*)(dh + off) = make_uint2(h0, h1);
    *(uint2*)(dl + off) = make_uint2(l0, l1);
}

// ===========================================================================
// proj: R14 structure — 2-stage k32, WAIT/sync/MMA/sync/prefetch
// grid (D_/128, MROWS/128, 3), block 256
// ===========================================================================
__global__ __launch_bounds__(256, 2) void proj_cp(
    const float* __restrict__ bq, const float* __restrict__ bk,
    const float* __restrict__ bv)
{
    extern __shared__ bf16 sm[];
    const uint32_t smb = s2u(sm);
    const int tid = threadIdx.x, w = tid >> 5, lane = tid & 31;
    const int n0 = blockIdx.x * 128, m0 = blockIdx.y * 128, z = blockIdx.z;
    const bf16* Xh = g_xh[z];
    const bf16* Xl = g_xl[z];
    const bf16* Wph = g_wh[z];
    const bf16* Wpl = g_wl[z];
    const float* bias = (z == 0) ? bq : (z == 1) ? bk : bv;
    bf16* outh = (z == 0) ? g_qh : (z == 1) ? g_kh : g_vh;
    bf16* outl = (z == 0) ? g_ql : (z == 1) ? g_kl : g_vl;
    const int m_off = (w & 3) * 32, n_off = (w >> 2) * 64;
    float acc[2][8][4] = {};

    auto pref = [&](uint32_t base, int k0) {
        #pragma unroll
        for (int i = 0; i < 4; i++) {                 // A: 128x32, hi+lo
            int lin = tid + i * 256;
            int pl = lin >> 9, rem = lin & 511, r = rem >> 2, c4 = rem & 3;
            const bf16* srcp = (pl ? Xl : Xh) + (size_t)(m0 + r) * D_ + k0 + c4 * 8;
            cpa16(base + (pl * ABP + r * ASTR + c4 * 8) * 2, srcp);
        }
        #pragma unroll
        for (int i = 0; i < 4; i++) {                 // B: 32x128, hi+lo
            int lin = tid + i * 256;
            int pl = lin >> 9, rem = lin & 511, r = rem >> 4, c8 = rem & 15;
            int col = n0 + c8 * 8;
            int h = col >> 6, j = col & 63;
            const bf16* srcp = (pl ? Wpl : Wph) + ((size_t)h * D_ + k0 + r) * DK + j;
            cpa16(base + (2 * ABP + pl * BBP + r * BW + c8 * 8) * 2, srcp);
        }
        CPA_COMMIT();
    };

    pref(smb, 0);
    pref(smb + STGP * 2, 32);
    for (int c = 0; c < 32; c++) {
        if (c < 31) { CPA_WAIT(1); } else { CPA_WAIT(0); }
        __syncthreads();
        bf16* st = sm + (c & 1) * STGP;
        warp_chunk128(st, st + ABP, st + 2 * ABP, st + 2 * ABP + BBP,
                      m_off, n_off, lane, acc);
        __syncthreads();
        if (c + 2 < 32)
            pref(smb + (c & 1) * (STGP * 2), (c + 2) * 32);
    }

    const int g = lane >> 2, q = lane & 3;
    const int h = (n0 + n_off) >> 6;
    #pragma unroll
    for (int mi = 0; mi < 2; mi++) {
        int m = m0 + m_off + mi * 16 + g;
        int b = m >> 10, s = m & 1023;
        size_t base0 = (((size_t)(b * H_ + h)) * S_ + s) * DK;
        size_t base1 = (((size_t)(b * H_ + h)) * S_ + s + 8) * DK;
        #pragma unroll
        for (int nj = 0; nj < 8; nj++) {
            int j0 = nj * 8 + q * 2;
            float bb0 = bias[h * DK + j0], bb1 = bias[h * DK + j0 + 1];
            float v0 = acc[mi][nj][0] + bb0, v1 = acc[mi][nj][1] + bb1;
            float v2 = acc[mi][nj][2] + bb0, v3 = acc[mi][nj][3] + bb1;
            uint32_t hp0 = packbf(v0, v1), hp1 = packbf(v2, v3);
            float h0 = __uint_as_float(hp0 << 16), h1 = __uint_as_float(hp0 & 0xffff0000u);
            float h2 = __uint_as_float(hp1 << 16), h3 = __uint_as_float(hp1 & 0xffff0000u);
            uint32_t lp0 = packbf(v0 - h0, v1 - h1), lp1 = packbf(v2 - h2, v3 - h3);
            *(uint32_t*)&outh[base0 + j0] = hp0;
            *(uint32_t*)&outl[base0 + j0] = lp0;
            *(uint32_t*)&outh[base1 + j0] = hp1;
            *(uint32_t*)&outl[base1 + j0] = lp1;
        }
    }
}

// ===========================================================================
// outproj: R15 structure — 3-stage k32, single barrier, prefetch-then-MMA
// grid (D_/128, MROWS/128), block 256
// ===========================================================================
__global__ __launch_bounds__(256, 2) void outproj_cp(
    const float* __restrict__ bo, float* __restrict__ out)
{
    extern __shared__ bf16 sm[];
    const uint32_t smb = s2u(sm);
    const int tid = threadIdx.x, w = tid >> 5, lane = tid & 31;
    const int n0 = blockIdx.x * 128, m0 = blockIdx.y * 128;
    const int m_off = (w & 3) * 32, n_off = (w >> 2) * 64;
    float acc[2][8][4] = {};

    auto pref = [&](int buf, int k0) {
        uint32_t base = smb + buf * (STGP * 2);
        const int h = k0 >> 6, j0 = k0 & 63;
        #pragma unroll
        for (int i = 0; i < 4; i++) {
            int lin = tid + i * 256;
            int pl = lin >> 9, rem = lin & 511, r = rem >> 2, c4 = rem & 3;
            int m = m0 + r;
            int b = m >> 10, s = m & 1023;
            const bf16* srcp = (pl ? g_cl : g_ch) +
                (((size_t)b * H_ + h) * S_ + s) * DK + j0 + c4 * 8;
            cpa16(base + (pl * ABP + r * ASTR + c4 * 8) * 2, srcp);
        }
        #pragma unroll
        for (int i = 0; i < 4; i++) {
            int lin = tid + i * 256;
            int pl = lin >> 9, rem = lin & 511, r = rem >> 4, c8 = rem & 15;
            const bf16* srcp = (pl ? g_wol : g_woh) + (size_t)(k0 + r) * D_ + n0 + c8 * 8;
            cpa16(base + (2 * ABP + pl * BBP + r * BW + c8 * 8) * 2, srcp);
        }
        CPA_COMMIT();
    };

    pref(0, 0);
    pref(1, 32);
    int buf = 0;
    for (int c = 0; c < 32; c++) {
        if (c < 31) { CPA_WAIT(1); } else { CPA_WAIT(0); }
        __syncthreads();
        if (c + 2 < 32) {
            int nb = buf + 2; if (nb >= 3) nb -= 3;
            pref(nb, (c + 2) * 32);
        }
        bf16* st = sm + buf * STGP;
        warp_chunk128(st, st + ABP, st + 2 * ABP, st + 2 * ABP + BBP,
                      m_off, n_off, lane, acc);
        if (++buf == 3) buf = 0;
    }

    const int g = lane >> 2, q = lane & 3;
    #pragma unroll
    for (int mi = 0; mi < 2; mi++) {
        int m = m0 + m_off + mi * 16 + g;
        float* d0 = out + (size_t)m * D_;
        float* d1 = out + (size_t)(m + 8) * D_;
        #pragma unroll
        for (int nj = 0; nj < 8; nj++) {
            int col = n0 + n_off + nj * 8 + q * 2;
            float bb0 = bo[col], bb1 = bo[col + 1];
            *(float2*)&d0[col] = make_float2(acc[mi][nj][0] + bb0, acc[mi][nj][1] + bb1);
            *(float2*)&d1[col] = make_float2(acc[mi][nj][2] + bb0, acc[mi][nj][3] + bb1);
        }
    }
}

// ===========================================================================
// Fused attention (unchanged from R12/R14)
// ===========================================================================
#define SC_STRW 1036
#define SC_ROWB (SC_STRW * 4)
#define SC_BYTES (32 * SC_ROWB)
#define KBUF_OFF SC_BYTES
#define KPLANE 18432
#define KBUF_SZ (2 * KPLANE)
#define Q_OFF (KBUF_OFF + 2 * KBUF_SZ)
#define FUSED_SMEM (Q_OFF + 2 * 4608)

__device__ __forceinline__ void attn_prefetch(
    char* smem, int bufidx, const bf16* ph, const bf16* pl,
    size_t bhS, int t0, int tid)
{
    uint32_t buf = s2u(smem + KBUF_OFF + bufidx * KBUF_SZ);
    #pragma unroll
    for (int i = 0; i < 8; i++) {
        int cid = tid + i * 256;
        int plane = cid >> 10, rem = cid & 1023;
        int row = rem >> 3, c16 = rem & 7;
        const bf16* src = (plane ? pl : ph) + (bhS + t0 + row) * DK + c16 * 8;
        cpa16(buf + plane * KPLANE + row * 144 + c16 * 16, src);
    }
    CPA_COMMIT();
}

__global__ __launch_bounds__(256) void attn_fused(
    const bf16* __restrict__ qh, const bf16* __restrict__ ql,
    const bf16* __restrict__ kh, const bf16* __restrict__ kl,
    const bf16* __restrict__ vh, const bf16* __restrict__ vl,
    float* __restrict__ attn, bf16* __restrict__ ctxh, bf16* __restrict__ ctxl)
{
    extern __shared__ char smem[];
    float* sc = (float*)smem;
    bf16* QH = (bf16*)(smem + Q_OFF);
    bf16* QL = (bf16*)(smem + Q_OFF + 4608);
    const uint32_t sc_base = s2u(smem);

    const int tid = threadIdx.x, w = tid >> 5, lane = tid & 31;
    const int s0 = blockIdx.x * 32;
    const int bh = blockIdx.y;
    const size_t bhS = (size_t)bh * S_;
    const int wm = w & 1, wn = w >> 1;
    const int g = lane >> 2, q = lane & 3;

    #pragma unroll
    for (int i = 0; i < 2; i++) {
        int lin = tid + i * 256;
        int plane = lin >> 8;
        int rem = lin & 255;
        int row = rem >> 3;
        int c16 = rem & 7;
        const bf16* src = (plane ? ql : qh) + (bhS + s0 + row) * DK + c16 * 8;
        bf16* dstp = (plane ? QL : QH) + row * BSTR + c16 * 8;
        *(uint4*)dstp = *(const uint4*)src;
    }

    attn_prefetch(smem, 0, kh, kl, bhS, 0, tid);
    attn_prefetch(smem, 1, kh, kl, bhS, 128, tid);
    __syncthreads();

    uint32_t aqh[4][4], aql[4][4];
    #pragma unroll
    for (int k4 = 0; k4 < 4; k4++) {
        ldsm4(aqh[k4], s2u(QH + (wm * 16 + (lane & 15)) * BSTR + k4 * 16 + (lane >> 4) * 8));
        ldsm4(aql[k4], s2u(QL + (wm * 16 + (lane & 15)) * BSTR + k4 * 16 + (lane >> 4) * 8));
    }

    for (int c = 0; c < 8; c++) {
        if (c < 7) { CPA_WAIT(1); } else { CPA_WAIT(0); }
        __syncthreads();

        bf16* KHb = (bf16*)(smem + KBUF_OFF + (c & 1) * KBUF_SZ);
        bf16* KLb = (bf16*)(smem + KBUF_OFF + (c & 1) * KBUF_SZ + KPLANE);
        float acc[4][4] = {};
        #pragma unroll
        for (int k4 = 0; k4 < 4; k4++) {
            uint32_t bh4[2][4], bl4[2][4];
            #pragma unroll
            for (int j = 0; j < 2; j++)
                ldsm4(bh4[j], s2u(KHb + (wn * 32 + j * 16 + (lane & 7) + ((lane >> 4) << 3)) * BSTR
                                  + k4 * 16 + ((lane >> 3) & 1) * 8));
            #pragma unroll
            for (int nj = 0; nj < 4; nj++)
                mmabf(acc[nj], aqh[k4], &bh4[nj >> 1][(nj & 1) * 2]);
            #pragma unroll
            for (int j = 0; j < 2; j++)
                ldsm4(bl4[j], s2u(KLb + (wn * 32 + j * 16 + (lane & 7) + ((lane >> 4) << 3)) * BSTR
                                  + k4 * 16 + ((lane >> 3) & 1) * 8));
            #pragma unroll
            for (int nj = 0; nj < 4; nj++)
                mmabf(acc[nj], aqh[k4], &bl4[nj >> 1][(nj & 1) * 2]);
            #pragma unroll
            for (int nj = 0; nj < 4; nj++)
                mmabf(acc[nj], aql[k4], &bh4[nj >> 1][(nj & 1) * 2]);
        }
        #pragma unroll
        for (int nj = 0; nj < 4; nj++) {
            int col = c * 128 + wn * 32 + nj * 8 + q * 2;
            *(float2*)&sc[(wm * 16 + g) * SC_STRW + col] =
                make_float2(acc[nj][0] * 0.125f, acc[nj][1] * 0.125f);
            *(float2*)&sc[(wm * 16 + g + 8) * SC_STRW + col] =
                make_float2(acc[nj][2] * 0.125f, acc[nj][3] * 0.125f);
        }
        __syncthreads();
        if (c + 2 < 8)
            attn_prefetch(smem, c & 1, kh, kl, bhS, (c + 2) * 128, tid);
    }

    attn_prefetch(smem, 0, vh, vl, bhS, 0, tid);
    attn_prefetch(smem, 1, vh, vl, bhS, 128, tid);

    #pragma unroll
    for (int rr = 0; rr < 4; rr++) {
        const int row = w * 4 + rr;
        float* prow = sc + row * SC_STRW;
        char* rowb = smem + row * SC_ROWB;
        float4 v[8];
        float mx = -1e30f;
        #pragma unroll
        for (int j = 0; j < 8; j++) {
            v[j] = *(const float4*)&prow[lane * 4 + j * 128];
            mx = fmaxf(mx, fmaxf(fmaxf(v[j].x, v[j].y), fmaxf(v[j].z, v[j].w)));
        }
        #pragma unroll
        for (int off = 16; off > 0; off >>= 1)
            mx = fmaxf(mx, __shfl_xor_sync(0xffffffffu, mx, off));
        float sum = 0.f;
        #pragma unroll
        for (int j = 0; j < 8; j++) {
            v[j].x = __expf(v[j].x - mx); v[j].y = __expf(v[j].y - mx);
            v[j].z = __expf(v[j].z - mx); v[j].w = __expf(v[j].w - mx);
            sum += (v[j].x + v[j].y) + (v[j].z + v[j].w);
        }
        #pragma unroll
        for (int off = 16; off > 0; off >>= 1)
            sum += __shfl_xor_sync(0xffffffffu, sum, off);
        const float inv = 1.0f / sum;
        float* grow = attn + (bhS + s0 + row) * S_;
        #pragma unroll
        for (int j = 0; j < 8; j++) {
            float4 o = make_float4(v[j].x * inv, v[j].y * inv, v[j].z * inv, v[j].w * inv);
            *(float4*)&grow[lane * 4 + j * 128] = o;
            uint32_t h01 = packbf(o.x, o.y);
            uint32_t h23 = packbf(o.z, o.w);
            float hx = __uint_as_float(h01 << 16), hy = __uint_as_float(h01 & 0xffff0000u);
            float hz = __uint_as_float(h23 << 16), hw = __uint_as_float(h23 & 0xffff0000u);
            uint32_t l01 = packbf(o.x - hx, o.y - hy);
            uint32_t l23 = packbf(o.z - hz, o.w - hw);
            *(uint2*)(rowb + lane * 8 + j * 256)        = make_uint2(h01, h23);
            *(uint2*)(rowb + 2048 + lane * 8 + j * 256) = make_uint2(l01, l23);
        }
    }
    __syncthreads();

    float acc2[2][4] = {};
    for (int c = 0; c < 8; c++) {
        if (c < 7) { CPA_WAIT(1); } else { CPA_WAIT(0); }
        __syncthreads();

        bf16* VHb = (bf16*)(smem + KBUF_OFF + (c & 1) * KBUF_SZ);
        bf16* VLb = (bf16*)(smem + KBUF_OFF + (c & 1) * KBUF_SZ + KPLANE);
        #pragma unroll
        for (int k4 = 0; k4 < 8; k4++) {
            int colb = c * 128 + k4 * 16;
            uint32_t abase = sc_base + (wm * 16 + (lane & 15)) * SC_ROWB
                             + (colb + (lane >> 4) * 8) * 2;
            uint32_t ah[4], al[4];
            ldsm4(ah, abase);
            ldsm4(al, abase + 2048);

            uint32_t bhf[4], blf[4];
            ldsm4t(bhf, s2u(VHb + (k4 * 16 + (lane & 15)) * BSTR + wn * 16 + (lane >> 4) * 8));
            ldsm4t(blf, s2u(VLb + (k4 * 16 + (lane & 15)) * BSTR + wn * 16 + (lane >> 4) * 8));
            #pragma unroll
            for (int nj = 0; nj < 2; nj++) {
                mmabf(acc2[nj], ah, &bhf[nj * 2]);
                mmabf(acc2[nj], ah, &blf[nj * 2]);
                mmabf(acc2[nj], al, &bhf[nj * 2]);
            }
        }
        __syncthreads();
        if (c + 2 < 8)
            attn_prefetch(smem, c & 1, vh, vl, bhS, (c + 2) * 128, tid);
    }

    #pragma unroll
    for (int nj = 0; nj < 2; nj++) {
        int col = wn * 16 + nj * 8 + q * 2;
        size_t i0 = (bhS + s0 + wm * 16 + g) * DK + col;
        size_t i1 = (bhS + s0 + wm * 16 + g + 8) * DK + col;
        uint32_t hp0 = packbf(acc2[nj][0], acc2[nj][1]);
        uint32_t hp1 = packbf(acc2[nj][2], acc2[nj][3]);
        float h0 = __uint_as_float(hp0 << 16), h1 = __uint_as_float(hp0 & 0xffff0000u);
        float h2 = __uint_as_float(hp1 << 16), h3 = __uint_as_float(hp1 & 0xffff0000u);
        uint32_t lp0 = packbf(acc2[nj][0] - h0, acc2[nj][1] - h1);
        uint32_t lp1 = packbf(acc2[nj][2] - h2, acc2[nj][3] - h3);
        *(uint32_t*)&ctxh[i0] = hp0;
        *(uint32_t*)&ctxl[i0] = lp0;
        *(uint32_t*)&ctxh[i1] = hp1;
        *(uint32_t*)&ctxl[i1] = lp1;
    }
}

// ---------------------------------------------------------------------------
extern "C" void kernel_launch(void* const* d_in, const int* in_sizes, int n_in,
                              void* d_out, int out_size)
{
    const float* query = (const float*)d_in[0];
    const float* key   = (const float*)d_in[1];
    const float* value = (const float*)d_in[2];
    const float* Wq    = (const float*)d_in[3];
    const float* bq    = (const float*)d_in[4];
    const float* Wk    = (const float*)d_in[5];
    const float* bk    = (const float*)d_in[6];
    const float* Wv    = (const float*)d_in[7];
    const float* bv    = (const float*)d_in[8];
    const float* Wo    = (const float*)d_in[9];
    const float* bo    = (const float*)d_in[10];
    float* out = (float*)d_out;

    bf16 *qh, *ql, *kh, *kl, *vh, *vl, *ch, *cl;
    float *attn_scratch;
    cudaGetSymbolAddress((void**)&qh, g_qh);
    cudaGetSymbolAddress((void**)&ql, g_ql);
    cudaGetSymbolAddress((void**)&kh, g_kh);
    cudaGetSymbolAddress((void**)&kl, g_kl);
    cudaGetSymbolAddress((void**)&vh, g_vh);
    cudaGetSymbolAddress((void**)&vl, g_vl);
    cudaGetSymbolAddress((void**)&ch, g_ch);
    cudaGetSymbolAddress((void**)&cl, g_cl);
    cudaGetSymbolAddress((void**)&attn_scratch, g_attn);

    const size_t out_elems  = (size_t)B_ * S_ * D_;
    const size_t attn_elems = (size_t)BH * S_ * S_;
    float* attn = ((size_t)out_size >= out_elems + attn_elems)
                      ? (out + out_elems) : attn_scratch;

    static int smem_set = 0;
    if (!smem_set) {
        cudaFuncSetAttribute(proj_cp, cudaFuncAttributeMaxDynamicSharedMemorySize, SMEM_P2);
        cudaFuncSetAttribute(outproj_cp, cudaFuncAttributeMaxDynamicSharedMemorySize, SMEM_P3);
        cudaFuncSetAttribute(attn_fused, cudaFuncAttributeMaxDynamicSharedMemorySize, FUSED_SMEM);
        smem_set = 1;
    }

    cvt_all<<<(CVT_UNITS + 255) / 256, 256>>>(query, key, value, Wq, Wk, Wv, Wo);
    proj_cp<<<dim3(D_ / 128, MROWS / 128, 3), 256, SMEM_P2>>>(bq, bk, bv);
    attn_fused<<<dim3(S_ / 32, BH), 256, FUSED_SMEM>>>(qh, ql, kh, kl, vh, vl, attn, ch, cl);
    outproj_cp<<<dim3(D_ / 128, MROWS / 128), 256, SMEM_P3>>>(bo, out);
}